// round 2
// baseline (speedup 1.0000x reference)
#include <cuda_runtime.h>
#include <cuda_bf16.h>

typedef unsigned long long ull;

// ---------------- scratch (no allocation allowed) ----------------
__device__ float g_mods[16 * 5 * 512];   // [b][layer][gam|bet]
__device__ float g_loss[16];             // per-b summed loss
__device__ float g_q[16 * 256];          // z_q_sum per b

// ---------------- f32x2 helpers ----------------
__device__ __forceinline__ ull fma2(ull a, ull b, ull c) {
    ull d;
    asm("fma.rn.f32x2 %0, %1, %2, %3;" : "=l"(d) : "l"(a), "l"(b), "l"(c));
    return d;
}
__device__ __forceinline__ float2 unpk(ull v) {
    float lo, hi;
    asm("mov.b64 {%0, %1}, %2;" : "=f"(lo), "=f"(hi) : "l"(v));
    float2 r; r.x = lo; r.y = hi; return r;
}

// =================================================================
// Kernel 1: residual VQ. grid=16 (one block per b), 1024 threads
// (one code per thread). loss via ||r_{s+1}||^2 = ||r_s||^2 + d_min.
// =================================================================
__global__ __launch_bounds__(1024)
void vq_kernel(const int* __restrict__ lidx,
               const float* __restrict__ latents,
               const float* __restrict__ emb) {
    __shared__ float r[256];
    __shared__ float q[256];
    __shared__ float redv[32];
    __shared__ int   redi[32];
    __shared__ float s_d, s_r2;
    __shared__ int   s_c;

    const int b = blockIdx.x, t = threadIdx.x;
    const int lane = t & 31, wid = t >> 5;

    if (t < 256) {
        const float* lp = latents + (size_t)lidx[b] * 1024;
        float z = lp[t] + lp[256 + t] + lp[512 + t] + lp[768 + t];
        r[t] = z; q[t] = 0.f;
    }
    __syncthreads();

    // ||z||^2
    float rz = (t < 256) ? r[t] * r[t] : 0.f;
    #pragma unroll
    for (int o = 16; o; o >>= 1) rz += __shfl_down_sync(~0u, rz, o);
    if (lane == 0) redv[wid] = rz;
    __syncthreads();
    if (t == 0) {
        float s = 0.f;
        #pragma unroll
        for (int w = 0; w < 32; w++) s += redv[w];
        s_r2 = s;
    }
    float loss = 0.f;   // thread 0 only
    __syncthreads();

    for (int s = 0; s < 4; ++s) {
        const float4* E4 = reinterpret_cast<const float4*>(
            emb + ((size_t)s * 1024 + t) * 256);
        const float4* r4 = reinterpret_cast<const float4*>(r);
        float n0 = 0.f, n1 = 0.f, d0 = 0.f, d1 = 0.f;
        #pragma unroll 8
        for (int i = 0; i < 64; i += 2) {
            float4 e = E4[i];     float4 rr = r4[i];
            n0 = fmaf(e.z, e.z, fmaf(e.w, e.w, fmaf(e.x, e.x, fmaf(e.y, e.y, n0))));
            d0 = fmaf(e.z, rr.z, fmaf(e.w, rr.w, fmaf(e.x, rr.x, fmaf(e.y, rr.y, d0))));
            e = E4[i + 1];        rr = r4[i + 1];
            n1 = fmaf(e.z, e.z, fmaf(e.w, e.w, fmaf(e.x, e.x, fmaf(e.y, e.y, n1))));
            d1 = fmaf(e.z, rr.z, fmaf(e.w, rr.w, fmaf(e.x, rr.x, fmaf(e.y, rr.y, d1))));
        }
        float dist = (n0 + n1) - 2.f * (d0 + d1);
        int ci = t;
        #pragma unroll
        for (int o = 16; o; o >>= 1) {
            float ov = __shfl_down_sync(~0u, dist, o);
            int   oi = __shfl_down_sync(~0u, ci,   o);
            if (ov < dist || (ov == dist && oi < ci)) { dist = ov; ci = oi; }
        }
        if (lane == 0) { redv[wid] = dist; redi[wid] = ci; }
        __syncthreads();
        if (wid == 0) {
            float v = redv[lane]; int c2 = redi[lane];
            #pragma unroll
            for (int o = 16; o; o >>= 1) {
                float ov = __shfl_down_sync(~0u, v,  o);
                int   oi = __shfl_down_sync(~0u, c2, o);
                if (ov < v || (ov == v && oi < c2)) { v = ov; c2 = oi; }
            }
            if (lane == 0) { s_d = v; s_c = c2; }
        }
        __syncthreads();
        if (t == 0) { loss += s_d + s_r2; s_r2 += s_d; }
        const int cmin = s_c;
        if (t < 256) {
            float e = emb[((size_t)s * 1024 + cmin) * 256 + t];
            q[t] += e; r[t] -= e;
        }
        __syncthreads();
    }
    if (t == 0) g_loss[b] = loss;
    if (t < 256) g_q[b * 256 + t] = q[t];
}

// =================================================================
// Kernel 2: FiLM mods GEMM. grid (5 layers, 4 h-chunks), 128 thr.
// =================================================================
__global__ __launch_bounds__(128)
void mods_kernel(const float* __restrict__ mod_W,
                 const float* __restrict__ mod_b) {
    __shared__ float qt[256 * 16];   // [d][b]
    const int l = blockIdx.x, ch = blockIdx.y, t = threadIdx.x;
    for (int i = t; i < 4096; i += 128) {
        int bb = i >> 8, d = i & 255;
        qt[d * 16 + bb] = g_q[i];
    }
    __syncthreads();
    const int h = ch * 128 + t;
    float acc[16];
    const float bias = mod_b[l * 512 + h];
    #pragma unroll
    for (int bb = 0; bb < 16; bb++) acc[bb] = bias;
    const float* Wp = mod_W + (size_t)l * 131072 + h;
    #pragma unroll 4
    for (int d = 0; d < 256; ++d) {
        float w = Wp[(size_t)d * 512];
        const float4* q4 = reinterpret_cast<const float4*>(qt + d * 16);
        float4 a = q4[0], c = q4[1], e = q4[2], f = q4[3];
        acc[0]  = fmaf(a.x, w, acc[0]);  acc[1]  = fmaf(a.y, w, acc[1]);
        acc[2]  = fmaf(a.z, w, acc[2]);  acc[3]  = fmaf(a.w, w, acc[3]);
        acc[4]  = fmaf(c.x, w, acc[4]);  acc[5]  = fmaf(c.y, w, acc[5]);
        acc[6]  = fmaf(c.z, w, acc[6]);  acc[7]  = fmaf(c.w, w, acc[7]);
        acc[8]  = fmaf(e.x, w, acc[8]);  acc[9]  = fmaf(e.y, w, acc[9]);
        acc[10] = fmaf(e.z, w, acc[10]); acc[11] = fmaf(e.w, w, acc[11]);
        acc[12] = fmaf(f.x, w, acc[12]); acc[13] = fmaf(f.y, w, acc[13]);
        acc[14] = fmaf(f.z, w, acc[14]); acc[15] = fmaf(f.w, w, acc[15]);
    }
    #pragma unroll
    for (int bb = 0; bb < 16; bb++)
        g_mods[bb * 2560 + l * 512 + h] = acc[bb];
}

// =================================================================
// Kernel 3: finalize vq_loss -> d_out[out_size-1]  (sum / 65536)
// =================================================================
__global__ void loss_kernel(float* out, int out_size) {
    if (threadIdx.x == 0) {
        float s = 0.f;
        #pragma unroll
        for (int i = 0; i < 16; ++i) s += g_loss[i];
        out[out_size - 1] = s * (1.0f / 65536.0f);
    }
}

// =================================================================
// Kernel 4: fused SIREN decoder.
// grid (64 tiles, 16 b), 512 thr, M_TILE=64.
// xsT transposed [k][m] (row stride 66), weights duplicated in smem
// (double-buffered 32-k panels). acc pairs along M via f32x2.
// Thread tile: 4 m (2 pairs) x 8 n (n = lane + 32j).
// =================================================================
#define RXS 66

__global__ __launch_bounds__(512, 1)
void dec_kernel(const float* __restrict__ coords,
                const float* __restrict__ W0g,
                const float* __restrict__ b0g,
                const float* __restrict__ Whg,
                const float* __restrict__ bhg,
                const float* __restrict__ Wlg,
                const float* __restrict__ blg,
                float* __restrict__ out) {
    extern __shared__ float sm[];
    float* xsT  = sm;              // 256*66 = 16896
    float* wb0  = xsT + 16896;     // 16384 (32k x 256n duplicated)
    float* wb1  = wb0 + 16384;     // 16384
    float* film = wb1 + 16384;     // 2048 (layers 1..4 gam|bet)
    float* w0s  = film + 2048;     // 768  (W0[2][256] + b0)
    float* wls  = w0s + 768;       // 772  (Wl 768 + bl 3 + pad)
    float* cs   = wls + 772;       // 128  coords

    const int b      = blockIdx.y;
    const int m_base = blockIdx.x * 64;
    const int t   = threadIdx.x;
    const int nt  = t & 31;
    const int wd  = t >> 5;
    const int m0  = wd * 4;

    // ---- stage constants ----
    for (int i = t; i < 2048; i += 512) film[i] = g_mods[b * 2560 + 512 + i];
    for (int i = t; i < 768;  i += 512) w0s[i] = (i < 512) ? W0g[i] : b0g[i - 512];
    for (int i = t; i < 771;  i += 512) wls[i] = (i < 768) ? Wlg[i] : blg[i - 768];
    if (t < 128) cs[t] = coords[((size_t)(b * 4096 + m_base)) * 2 + t];
    __syncthreads();

    // ---- layer 0: xsT[n][m] = sin(30*(coords@W0 + b0)) ----
    const float2* cs2 = reinterpret_cast<const float2*>(cs);
    for (int i = t; i < 16384; i += 512) {
        const int m = i & 63, n = i >> 6;
        float2 c2 = cs2[m];
        float pre = fmaf(c2.x, w0s[n], fmaf(c2.y, w0s[256 + n], w0s[512 + n]));
        xsT[n * RXS + m] = __sinf(30.0f * pre);
    }

    float* wbuf[2] = { wb0, wb1 };
    ull acc[2][8];

    for (int l = 0; l < 4; ++l) {
        const float* W = Whg + (size_t)l * 65536;
        #pragma unroll
        for (int p = 0; p < 2; ++p)
            #pragma unroll
            for (int j = 0; j < 8; ++j) acc[p][j] = 0ull;

        // prologue: fill panel 0 into wb0 (duplicated)
        {
            const float4* Wg4 = reinterpret_cast<const float4*>(W);
            float4* dst4 = reinterpret_cast<float4*>(wbuf[0]);
            #pragma unroll
            for (int i = 0; i < 4; ++i) {
                int idx = t + i * 512;
                float4 v = Wg4[idx];
                int k = idx >> 6, n4 = idx & 63;
                float4 lo; lo.x = v.x; lo.y = v.x; lo.z = v.y; lo.w = v.y;
                float4 hi; hi.x = v.z; hi.y = v.z; hi.z = v.w; hi.w = v.w;
                dst4[k * 128 + n4 * 2]     = lo;
                dst4[k * 128 + n4 * 2 + 1] = hi;
            }
        }

        for (int kp = 0; kp < 8; ++kp) {
            __syncthreads();
            if (kp < 7) {   // prefetch next panel into other buffer
                const float4* Wg4 = reinterpret_cast<const float4*>(W + (kp + 1) * 8192);
                float4* dst4 = reinterpret_cast<float4*>(wbuf[(kp + 1) & 1]);
                #pragma unroll
                for (int i = 0; i < 4; ++i) {
                    int idx = t + i * 512;
                    float4 v = Wg4[idx];
                    int k = idx >> 6, n4 = idx & 63;
                    float4 lo; lo.x = v.x; lo.y = v.x; lo.z = v.y; lo.w = v.y;
                    float4 hi; hi.x = v.z; hi.y = v.z; hi.z = v.w; hi.w = v.w;
                    dst4[k * 128 + n4 * 2]     = lo;
                    dst4[k * 128 + n4 * 2 + 1] = hi;
                }
            }
            const ull* wbU = reinterpret_cast<const ull*>(wbuf[kp & 1]);
            const int kg0 = kp * 32;
            #pragma unroll 8
            for (int k = 0; k < 32; ++k) {
                const ull* xr = reinterpret_cast<const ull*>(xsT + (kg0 + k) * RXS);
                const ull a01 = xr[m0 >> 1];
                const ull a23 = xr[(m0 >> 1) + 1];
                const ull* wr = wbU + k * 256;
                #pragma unroll
                for (int j = 0; j < 8; ++j) {
                    const ull w = wr[nt + 32 * j];
                    acc[0][j] = fma2(a01, w, acc[0][j]);
                    acc[1][j] = fma2(a23, w, acc[1][j]);
                }
            }
        }
        __syncthreads();   // all xsT reads for this layer complete

        // ---- FiLM + sin epilogue -> xsT (next layer input) ----
        const float* fg  = film + l * 512;
        const float* fb  = fg + 256;
        const float* bhl = bhg + l * 256;
        #pragma unroll
        for (int j = 0; j < 8; ++j) {
            const int n = nt + 32 * j;
            const float g  = 1.0f + fg[n];
            const float be = fb[n];
            const float bh = bhl[n];
            #pragma unroll
            for (int p = 0; p < 2; ++p) {
                float2 y = unpk(acc[p][j]);
                float2 o;
                o.x = __sinf(30.0f * fmaf(y.x + bh, g, be));
                o.y = __sinf(30.0f * fmaf(y.y + bh, g, be));
                *reinterpret_cast<float2*>(xsT + n * RXS + m0 + 2 * p) = o;
            }
        }
    }
    __syncthreads();

    // ---- output head: values = x @ Wl + bl ----
    if (t < 192) {
        const int m = t / 3, c = t - m * 3;
        float a0 = 0.f, a1 = 0.f, a2 = 0.f, a3 = 0.f;
        #pragma unroll 8
        for (int k = 0; k < 256; k += 4) {
            a0 = fmaf(xsT[(k)     * RXS + m], wls[(k)     * 3 + c], a0);
            a1 = fmaf(xsT[(k + 1) * RXS + m], wls[(k + 1) * 3 + c], a1);
            a2 = fmaf(xsT[(k + 2) * RXS + m], wls[(k + 2) * 3 + c], a2);
            a3 = fmaf(xsT[(k + 3) * RXS + m], wls[(k + 3) * 3 + c], a3);
        }
        out[((size_t)(b * 4096 + m_base + m)) * 3 + c] =
            (a0 + a1) + (a2 + a3) + wls[768 + c];
    }
}

// =================================================================
extern "C" void kernel_launch(void* const* d_in, const int* in_sizes, int n_in,
                              void* d_out, int out_size) {
    const float* coords  = (const float*)d_in[0];
    const int*   lidx    = (const int*)  d_in[1];
    const float* latents = (const float*)d_in[2];
    const float* emb     = (const float*)d_in[3];
    const float* mod_W   = (const float*)d_in[4];
    const float* mod_b   = (const float*)d_in[5];
    const float* W0      = (const float*)d_in[6];
    const float* b0      = (const float*)d_in[7];
    const float* Wh      = (const float*)d_in[8];
    const float* bh      = (const float*)d_in[9];
    const float* Wl      = (const float*)d_in[10];
    const float* bl      = (const float*)d_in[11];
    float* out = (float*)d_out;

    vq_kernel<<<16, 1024>>>(lidx, latents, emb);
    mods_kernel<<<dim3(5, 4), 128>>>(mod_W, mod_b);
    loss_kernel<<<1, 32>>>(out, out_size);

    const size_t smem = (16896 + 16384 + 16384 + 2048 + 768 + 772 + 128) * sizeof(float);
    cudaFuncSetAttribute(dec_kernel, cudaFuncAttributeMaxDynamicSharedMemorySize, (int)smem);
    dec_kernel<<<dim3(64, 16), 512, smem>>>(coords, W0, b0, Wh, bh, Wl, bl, out);
}

// round 3
// speedup vs baseline: 1.7165x; 1.7165x over previous
#include <cuda_runtime.h>
#include <cuda_bf16.h>

typedef unsigned long long ull;

// ---------------- scratch (no allocation allowed) ----------------
__device__ float g_mods[16 * 5 * 512];   // [b][layer][gam|bet]
__device__ float g_loss[16];             // per-b summed loss
__device__ float g_q[16 * 256];          // z_q_sum per b

// ---------------- f32x2 helpers ----------------
__device__ __forceinline__ ull dupf(float x) {
    ull r;
    asm("mov.b64 %0, {%1, %1};" : "=l"(r) : "f"(x));
    return r;
}
__device__ __forceinline__ ull fma2(ull a, ull b, ull c) {
    ull d;
    asm("fma.rn.f32x2 %0, %1, %2, %3;" : "=l"(d) : "l"(a), "l"(b), "l"(c));
    return d;
}
__device__ __forceinline__ float2 unpk(ull v) {
    float lo, hi;
    asm("mov.b64 {%0, %1}, %2;" : "=f"(lo), "=f"(hi) : "l"(v));
    float2 r; r.x = lo; r.y = hi; return r;
}

// =================================================================
// Kernel 1: residual VQ. grid=16 (one block per b), 1024 threads
// =================================================================
__global__ __launch_bounds__(1024)
void vq_kernel(const int* __restrict__ lidx,
               const float* __restrict__ latents,
               const float* __restrict__ emb) {
    __shared__ float r[256];
    __shared__ float q[256];
    __shared__ float redv[32];
    __shared__ int   redi[32];
    __shared__ float s_d, s_r2;
    __shared__ int   s_c;

    const int b = blockIdx.x, t = threadIdx.x;
    const int lane = t & 31, wid = t >> 5;

    if (t < 256) {
        const float* lp = latents + (size_t)lidx[b] * 1024;
        float z = lp[t] + lp[256 + t] + lp[512 + t] + lp[768 + t];
        r[t] = z; q[t] = 0.f;
    }
    __syncthreads();

    float rz = (t < 256) ? r[t] * r[t] : 0.f;
    #pragma unroll
    for (int o = 16; o; o >>= 1) rz += __shfl_down_sync(~0u, rz, o);
    if (lane == 0) redv[wid] = rz;
    __syncthreads();
    if (t == 0) {
        float s = 0.f;
        #pragma unroll
        for (int w = 0; w < 32; w++) s += redv[w];
        s_r2 = s;
    }
    float loss = 0.f;
    __syncthreads();

    for (int s = 0; s < 4; ++s) {
        const float4* E4 = reinterpret_cast<const float4*>(
            emb + ((size_t)s * 1024 + t) * 256);
        const float4* r4 = reinterpret_cast<const float4*>(r);
        float n0 = 0.f, n1 = 0.f, d0 = 0.f, d1 = 0.f;
        #pragma unroll 8
        for (int i = 0; i < 64; i += 2) {
            float4 e = E4[i];     float4 rr = r4[i];
            n0 = fmaf(e.z, e.z, fmaf(e.w, e.w, fmaf(e.x, e.x, fmaf(e.y, e.y, n0))));
            d0 = fmaf(e.z, rr.z, fmaf(e.w, rr.w, fmaf(e.x, rr.x, fmaf(e.y, rr.y, d0))));
            e = E4[i + 1];        rr = r4[i + 1];
            n1 = fmaf(e.z, e.z, fmaf(e.w, e.w, fmaf(e.x, e.x, fmaf(e.y, e.y, n1))));
            d1 = fmaf(e.z, rr.z, fmaf(e.w, rr.w, fmaf(e.x, rr.x, fmaf(e.y, rr.y, d1))));
        }
        float dist = (n0 + n1) - 2.f * (d0 + d1);
        int ci = t;
        #pragma unroll
        for (int o = 16; o; o >>= 1) {
            float ov = __shfl_down_sync(~0u, dist, o);
            int   oi = __shfl_down_sync(~0u, ci,   o);
            if (ov < dist || (ov == dist && oi < ci)) { dist = ov; ci = oi; }
        }
        if (lane == 0) { redv[wid] = dist; redi[wid] = ci; }
        __syncthreads();
        if (wid == 0) {
            float v = redv[lane]; int c2 = redi[lane];
            #pragma unroll
            for (int o = 16; o; o >>= 1) {
                float ov = __shfl_down_sync(~0u, v,  o);
                int   oi = __shfl_down_sync(~0u, c2, o);
                if (ov < v || (ov == v && oi < c2)) { v = ov; c2 = oi; }
            }
            if (lane == 0) { s_d = v; s_c = c2; }
        }
        __syncthreads();
        if (t == 0) { loss += s_d + s_r2; s_r2 += s_d; }
        const int cmin = s_c;
        if (t < 256) {
            float e = emb[((size_t)s * 1024 + cmin) * 256 + t];
            q[t] += e; r[t] -= e;
        }
        __syncthreads();
    }
    if (t == 0) g_loss[b] = loss;
    if (t < 256) g_q[b * 256 + t] = q[t];
}

// =================================================================
// Kernel 2: FiLM mods GEMM. grid (5 layers, 4 h-chunks), 128 thr.
// =================================================================
__global__ __launch_bounds__(128)
void mods_kernel(const float* __restrict__ mod_W,
                 const float* __restrict__ mod_b) {
    __shared__ float qt[256 * 16];   // [d][b]
    const int l = blockIdx.x, ch = blockIdx.y, t = threadIdx.x;
    for (int i = t; i < 4096; i += 128) {
        int bb = i >> 8, d = i & 255;
        qt[d * 16 + bb] = g_q[i];
    }
    __syncthreads();
    const int h = ch * 128 + t;
    float acc[16];
    const float bias = mod_b[l * 512 + h];
    #pragma unroll
    for (int bb = 0; bb < 16; bb++) acc[bb] = bias;
    const float* Wp = mod_W + (size_t)l * 131072 + h;
    #pragma unroll 4
    for (int d = 0; d < 256; ++d) {
        float w = Wp[(size_t)d * 512];
        const float4* q4 = reinterpret_cast<const float4*>(qt + d * 16);
        float4 a = q4[0], c = q4[1], e = q4[2], f = q4[3];
        acc[0]  = fmaf(a.x, w, acc[0]);  acc[1]  = fmaf(a.y, w, acc[1]);
        acc[2]  = fmaf(a.z, w, acc[2]);  acc[3]  = fmaf(a.w, w, acc[3]);
        acc[4]  = fmaf(c.x, w, acc[4]);  acc[5]  = fmaf(c.y, w, acc[5]);
        acc[6]  = fmaf(c.z, w, acc[6]);  acc[7]  = fmaf(c.w, w, acc[7]);
        acc[8]  = fmaf(e.x, w, acc[8]);  acc[9]  = fmaf(e.y, w, acc[9]);
        acc[10] = fmaf(e.z, w, acc[10]); acc[11] = fmaf(e.w, w, acc[11]);
        acc[12] = fmaf(f.x, w, acc[12]); acc[13] = fmaf(f.y, w, acc[13]);
        acc[14] = fmaf(f.z, w, acc[14]); acc[15] = fmaf(f.w, w, acc[15]);
    }
    #pragma unroll
    for (int bb = 0; bb < 16; bb++)
        g_mods[bb * 2560 + l * 512 + h] = acc[bb];
}

// =================================================================
// Kernel 3: finalize vq_loss -> d_out[out_size-1]  (sum / 65536)
// =================================================================
__global__ void loss_kernel(float* out, int out_size) {
    if (threadIdx.x == 0) {
        float s = 0.f;
        #pragma unroll
        for (int i = 0; i < 16; ++i) s += g_loss[i];
        out[out_size - 1] = s * (1.0f / 65536.0f);
    }
}

// =================================================================
// Kernel 4: fused SIREN decoder.
// grid (64 tiles, 16 b), 256 thr, M_TILE=64, thread tile 8m x 8n.
// xs [m][k], n-paired f32x2 acc, x via warp-uniform broadcast LDS,
// 16-k weight panels double-buffered, prefetch held in registers.
// =================================================================
__global__ __launch_bounds__(256, 2)
void dec_kernel(const float* __restrict__ coords,
                const float* __restrict__ W0g,
                const float* __restrict__ b0g,
                const float* __restrict__ Whg,
                const float* __restrict__ bhg,
                const float* __restrict__ Wlg,
                const float* __restrict__ blg,
                float* __restrict__ out) {
    extern __shared__ float sm[];
    float* xs   = sm;              // 64*256 = 16384
    float* wb   = xs + 16384;      // 2 * 16*256 = 8192
    float* film = wb + 8192;       // 2048 (layers 1..4 gam|bet)
    float* w0s  = film + 2048;     // 768
    float* wls  = w0s + 768;       // 772 (Wl 768 + bl 3 + pad)
    float* cs   = wls + 772;       // 128

    const int b      = blockIdx.y;
    const int m_base = blockIdx.x * 64;
    const int t  = threadIdx.x;
    const int nt = t & 31;
    const int wd = t >> 5;         // 8 warps
    const int m0 = wd * 8;
    const int nA = nt * 4;
    const int nB = 128 + nt * 4;
    const int nt2 = nt * 2;

    // ---- stage constants ----
    for (int i = t; i < 2048; i += 256) film[i] = g_mods[b * 2560 + 512 + i];
    for (int i = t; i < 768;  i += 256) w0s[i] = (i < 512) ? W0g[i] : b0g[i - 512];
    for (int i = t; i < 771;  i += 256) wls[i] = (i < 768) ? Wlg[i] : blg[i - 768];
    if (t < 128) cs[t] = coords[((size_t)(b * 4096 + m_base)) * 2 + t];
    __syncthreads();

    // ---- layer 0: xs[m][n] = sin(30*(coords@W0 + b0)) ----
    const float2* cs2 = reinterpret_cast<const float2*>(cs);
    for (int i = t; i < 16384; i += 256) {
        const int m = i >> 8, n = i & 255;
        float2 c2 = cs2[m];
        float pre = fmaf(c2.x, w0s[n], fmaf(c2.y, w0s[256 + n], w0s[512 + n]));
        xs[m * 256 + n] = __sinf(30.0f * pre);
    }

    ull acc[8][4];
    #pragma unroll
    for (int mi = 0; mi < 8; ++mi)
        #pragma unroll
        for (int j = 0; j < 4; ++j) acc[mi][j] = 0ull;

    // prefetch panel 0 (16k x 256n = 4096 floats; 4 float4/thread)
    float4 pf[4];
    {
        const float4* Wg4 = reinterpret_cast<const float4*>(Whg);
        #pragma unroll
        for (int i = 0; i < 4; ++i) pf[i] = Wg4[t + i * 256];
    }

    // flattened 64-panel loop (4 layers x 16 panels)
    for (int p = 0; p < 64; ++p) {
        float* buf = wb + (p & 1) * 4096;
        {   // commit prefetched panel
            float4* b4 = reinterpret_cast<float4*>(buf);
            #pragma unroll
            for (int i = 0; i < 4; ++i) b4[t + i * 256] = pf[i];
        }
        __syncthreads();   // panel + (at layer start) epilogue xs visible

        if (p < 63) {      // prefetch next panel
            const float4* Wg4 = reinterpret_cast<const float4*>(
                Whg + (size_t)((p + 1) >> 4) * 65536 + ((p + 1) & 15) * 4096);
            #pragma unroll
            for (int i = 0; i < 4; ++i) pf[i] = Wg4[t + i * 256];
        }

        const int kg0 = (p & 15) * 16;
        #pragma unroll
        for (int k2 = 0; k2 < 8; ++k2) {
            const int kk = 2 * k2;
            float2 xv[8];
            #pragma unroll
            for (int mi = 0; mi < 8; ++mi)
                xv[mi] = *reinterpret_cast<const float2*>(
                    xs + (m0 + mi) * 256 + kg0 + kk);   // warp-uniform broadcast

            const ull* w0r = reinterpret_cast<const ull*>(buf + kk * 256);
            const ull* w1r = reinterpret_cast<const ull*>(buf + kk * 256 + 256);
            const ull b00 = w0r[nt2],      b01 = w0r[nt2 + 1];
            const ull b02 = w0r[64 + nt2], b03 = w0r[64 + nt2 + 1];
            const ull b10 = w1r[nt2],      b11 = w1r[nt2 + 1];
            const ull b12 = w1r[64 + nt2], b13 = w1r[64 + nt2 + 1];

            #pragma unroll
            for (int mi = 0; mi < 8; ++mi) {
                const ull a0 = dupf(xv[mi].x);
                const ull a1 = dupf(xv[mi].y);
                acc[mi][0] = fma2(a0, b00, fma2(a1, b10, acc[mi][0]));
                acc[mi][1] = fma2(a0, b01, fma2(a1, b11, acc[mi][1]));
                acc[mi][2] = fma2(a0, b02, fma2(a1, b12, acc[mi][2]));
                acc[mi][3] = fma2(a0, b03, fma2(a1, b13, acc[mi][3]));
            }
        }

        if ((p & 15) == 15) {
            __syncthreads();   // all xs reads of this layer complete
            const int l = p >> 4;
            const float* fg  = film + l * 512;
            const float* fb  = fg + 256;
            const float* bhl = bhg + l * 256;
            float gA[4], beA[4], bhA[4], gB[4], beB[4], bhB[4];
            #pragma unroll
            for (int j = 0; j < 4; ++j) {
                gA[j] = 1.0f + fg[nA + j]; beA[j] = fb[nA + j]; bhA[j] = bhl[nA + j];
                gB[j] = 1.0f + fg[nB + j]; beB[j] = fb[nB + j]; bhB[j] = bhl[nB + j];
            }
            #pragma unroll
            for (int mi = 0; mi < 8; ++mi) {
                float4 oA, oB;
                float2 y;
                y = unpk(acc[mi][0]);
                oA.x = __sinf(30.0f * fmaf(y.x + bhA[0], gA[0], beA[0]));
                oA.y = __sinf(30.0f * fmaf(y.y + bhA[1], gA[1], beA[1]));
                y = unpk(acc[mi][1]);
                oA.z = __sinf(30.0f * fmaf(y.x + bhA[2], gA[2], beA[2]));
                oA.w = __sinf(30.0f * fmaf(y.y + bhA[3], gA[3], beA[3]));
                y = unpk(acc[mi][2]);
                oB.x = __sinf(30.0f * fmaf(y.x + bhB[0], gB[0], beB[0]));
                oB.y = __sinf(30.0f * fmaf(y.y + bhB[1], gB[1], beB[1]));
                y = unpk(acc[mi][3]);
                oB.z = __sinf(30.0f * fmaf(y.x + bhB[2], gB[2], beB[2]));
                oB.w = __sinf(30.0f * fmaf(y.y + bhB[3], gB[3], beB[3]));
                *reinterpret_cast<float4*>(xs + (m0 + mi) * 256 + nA) = oA;
                *reinterpret_cast<float4*>(xs + (m0 + mi) * 256 + nB) = oB;
                acc[mi][0] = 0ull; acc[mi][1] = 0ull;
                acc[mi][2] = 0ull; acc[mi][3] = 0ull;
            }
            // next panel's top-of-loop barrier publishes these xs writes
        }
    }
    __syncthreads();

    // ---- output head: values = x @ Wl + bl ----
    if (t < 192) {
        const int m = t / 3, c = t - m * 3;
        float a0 = 0.f, a1 = 0.f, a2 = 0.f, a3 = 0.f;
        const float* xr = xs + m * 256;
        #pragma unroll 8
        for (int k = 0; k < 256; k += 4) {
            a0 = fmaf(xr[k],     wls[(k)     * 3 + c], a0);
            a1 = fmaf(xr[k + 1], wls[(k + 1) * 3 + c], a1);
            a2 = fmaf(xr[k + 2], wls[(k + 2) * 3 + c], a2);
            a3 = fmaf(xr[k + 3], wls[(k + 3) * 3 + c], a3);
        }
        out[((size_t)(b * 4096 + m_base + m)) * 3 + c] =
            (a0 + a1) + (a2 + a3) + wls[768 + c];
    }
}

// =================================================================
extern "C" void kernel_launch(void* const* d_in, const int* in_sizes, int n_in,
                              void* d_out, int out_size) {
    const float* coords  = (const float*)d_in[0];
    const int*   lidx    = (const int*)  d_in[1];
    const float* latents = (const float*)d_in[2];
    const float* emb     = (const float*)d_in[3];
    const float* mod_W   = (const float*)d_in[4];
    const float* mod_b   = (const float*)d_in[5];
    const float* W0      = (const float*)d_in[6];
    const float* b0      = (const float*)d_in[7];
    const float* Wh      = (const float*)d_in[8];
    const float* bh      = (const float*)d_in[9];
    const float* Wl      = (const float*)d_in[10];
    const float* bl      = (const float*)d_in[11];
    float* out = (float*)d_out;

    vq_kernel<<<16, 1024>>>(lidx, latents, emb);
    mods_kernel<<<dim3(5, 4), 128>>>(mod_W, mod_b);
    loss_kernel<<<1, 32>>>(out, out_size);

    const size_t smem = (16384 + 8192 + 2048 + 768 + 772 + 128) * sizeof(float); // 113168 B
    cudaFuncSetAttribute(dec_kernel, cudaFuncAttributeMaxDynamicSharedMemorySize, (int)smem);
    dec_kernel<<<dim3(64, 16), 256, smem>>>(coords, W0, b0, Wh, bh, Wl, bl, out);
}